// round 15
// baseline (speedup 1.0000x reference)
#include <cuda_runtime.h>
#include <cuda_fp16.h>
#include <math.h>
#include <float.h>
#include <stdint.h>

#define NN 4096
#define HID 256
#define RANK0 1228

// k_mma dyn smem byte offsets
#define WHO 0u
#define WBS 10240u     // w-hi buf: 128 x 40 halves
#define VHO 20480u
#define VBS 5120u      // v buf: 64 x 40 halves
#define VLO 30720u
#define SMT 40960

__device__ __align__(128) float  g_value[2ull * NN * HID];   // (b, j, h*64+k)
__device__ float2 g_stats[2 * NN];
__device__ __align__(128) __half g_vhi[8ull * 64 * NN];      // (b*4+h, k, j)
__device__ __align__(128) __half g_vlo[8ull * 64 * NN];

__device__ __forceinline__ void cpa16(uint32_t dst, const void* src) {
    asm volatile("cp.async.cg.shared.global [%0], [%1], 16;" :: "r"(dst), "l"(src));
}
__device__ __forceinline__ uint32_t pk(__half a, __half b) {
    __half2 h = __halves2half2(a, b);
    return *(uint32_t*)&h;
}
// monotone bin classification; used identically in both passes
__device__ __forceinline__ int binof(float f, int attempt) {
    if (attempt == 0) {
        if (f < 0.26f) return -2;
        int b = (int)((f - 0.26f) * 3200.f);
        return (b > 255) ? -1 : b;
    }
    int b = (int)(f * 256.f);
    return b < 0 ? 0 : (b > 255 ? 255 : b);
}
#define LDSM4(r0, r1, r2, r3, a) \
    asm volatile("ldmatrix.sync.aligned.m8n8.x4.shared.b16 {%0,%1,%2,%3},[%4];" \
        : "=r"(r0), "=r"(r1), "=r"(r2), "=r"(r3) : "r"(a))
#define MMA(d, a0, a1, a2, a3, b0, b1) \
    asm volatile("mma.sync.aligned.m16n8k16.row.col.f32.f16.f16.f32 " \
        "{%0,%1,%2,%3},{%4,%5,%6,%7},{%8,%9},{%0,%1,%2,%3};" \
        : "+f"((d)[0]), "+f"((d)[1]), "+f"((d)[2]), "+f"((d)[3]) \
        : "r"(a0), "r"(a1), "r"(a2), "r"(a3), "r"(b0), "r"(b1))

// ---------------------------------------------------------------------------
// k_pre: blocks [0,1024) -> g_value (per-head, 32 rows x 64 cols each)
//        blocks [1024,9216) -> g_stats (histogram select, verbatim logic)
// ---------------------------------------------------------------------------
__global__ void __launch_bounds__(256, 4) k_pre(const float* __restrict__ x,
                                                const float* __restrict__ wgt,
                                                const float* __restrict__ m) {
    __shared__ __align__(16) float u_sm[3104];
    const int t = threadIdx.x;
    if (blockIdx.x < 1024) {
        float* wsh = u_sm;            // 32 x 64
        float* xsh = u_sm + 2048;     // 32 x 33
        const int jt = blockIdx.x >> 2, h = blockIdx.x & 3;
        const size_t base = (size_t)jt * 32 * HID;
        const int jj = t >> 3, cg = t & 7;
        float4 a0 = make_float4(0.f, 0.f, 0.f, 0.f);
        float4 a1 = make_float4(0.f, 0.f, 0.f, 0.f);
        for (int ct = 0; ct < 8; ++ct) {
            __syncthreads();
#pragma unroll
            for (int s = 0; s < 8; ++s) {
                int idx = t + 256 * s;
                int cc = idx >> 6, col = idx & 63;
                wsh[idx] = wgt[h * 16384 + (ct * 32 + cc) * 64 + col];
            }
#pragma unroll
            for (int s = 0; s < 4; ++s) {
                int idx = t + 256 * s;
                int jr = idx >> 5, cc = idx & 31;
                xsh[jr * 33 + cc] = x[base + (size_t)jr * HID + ct * 32 + cc];
            }
            __syncthreads();
#pragma unroll 4
            for (int cc = 0; cc < 32; ++cc) {
                float xv = xsh[jj * 33 + cc];
                float4 w0 = *(const float4*)(wsh + cc * 64 + cg * 8);
                float4 w1 = *(const float4*)(wsh + cc * 64 + cg * 8 + 4);
                a0.x = fmaf(xv, w0.x, a0.x); a0.y = fmaf(xv, w0.y, a0.y);
                a0.z = fmaf(xv, w0.z, a0.z); a0.w = fmaf(xv, w0.w, a0.w);
                a1.x = fmaf(xv, w1.x, a1.x); a1.y = fmaf(xv, w1.y, a1.y);
                a1.z = fmaf(xv, w1.z, a1.z); a1.w = fmaf(xv, w1.w, a1.w);
            }
        }
        float* orow = g_value + base + (size_t)jj * HID + h * 64 + cg * 8;
        *(float4*)orow       = a0;
        *(float4*)(orow + 4) = a1;
        return;
    }

    const int row = blockIdx.x - 1024;
    const float* p = m + (size_t)row * NN;
    float*    list = u_sm;
    unsigned* hist = (unsigned*)(u_sm + 1024);
    __shared__ unsigned wsum[8];
    __shared__ int s_clo, s_cnt, s_bina, s_binb, s_excla, s_fail;
    const int lane = t & 31, wid = t >> 5;

    float4 vr[4];
#pragma unroll
    for (int s = 0; s < 4; ++s) vr[s] = *(const float4*)(p + 4 * (t + 256 * s));
    float fv[16];
#pragma unroll
    for (int s = 0; s < 4; ++s) {
        fv[s * 4 + 0] = vr[s].x; fv[s * 4 + 1] = vr[s].y;
        fv[s * 4 + 2] = vr[s].z; fv[s * 4 + 3] = vr[s].w;
    }

    bool done = false;
    for (int attempt = 0; attempt < 2 && !done; ++attempt) {
        __syncthreads();
        if (t == 0) { s_clo = 0; s_cnt = 0; s_fail = 0; }
        hist[t] = 0;
        __syncthreads();
        int my_lo = 0;
#pragma unroll
        for (int q = 0; q < 16; ++q) {
            int b = binof(fv[q], attempt);
            if (b == -2) my_lo++;
            else if (b >= 0) atomicAdd(&hist[b], 1u);
        }
        if (my_lo) atomicAdd((unsigned*)&s_clo, (unsigned)my_lo);
        __syncthreads();
        const int c_lo = s_clo;
        const unsigned hv = hist[t];

        unsigned v = hv;
#pragma unroll
        for (int d = 1; d < 32; d <<= 1) {
            unsigned nb = __shfl_up_sync(0xffffffffu, v, d);
            if (lane >= d) v += nb;
        }
        if (lane == 31) wsum[wid] = v;
        __syncthreads();
        if (t < 8) {
            unsigned xsc = wsum[t];
#pragma unroll
            for (int d = 1; d < 8; d <<= 1) {
                unsigned nb = __shfl_up_sync(0x000000ffu, xsc, d);
                if (t >= d) xsc += nb;
            }
            wsum[t] = xsc;
        }
        __syncthreads();
        const unsigned off = (wid > 0) ? wsum[wid - 1] : 0u;
        const int incl = (int)(v + off);
        const int excl = incl - (int)hv;
        const int total = (int)wsum[7];

        const int want_a = RANK0 - c_lo;
        const int want_b = want_a + 1;
        if (want_a < 0 || want_b >= total) continue;

        if (excl <= want_a && want_a < incl) { s_bina = t; s_excla = excl; }
        if (excl <= want_b && want_b < incl) { s_binb = t; }
        __syncthreads();
        if (t == s_binb && incl - s_excla > 1024) s_fail = 1;
        __syncthreads();
        if (s_fail) continue;
        const int ba = s_bina, bb = s_binb;
#pragma unroll
        for (int q = 0; q < 16; ++q) {
            int b = binof(fv[q], attempt);
            if (b >= ba && b <= bb) list[atomicAdd(&s_cnt, 1)] = fv[q];
        }
        __syncthreads();
        if (t == 0) {
            const int n = s_cnt;
            for (int a = 1; a < n; ++a) {
                float key = list[a];
                int bq = a - 1;
                while (bq >= 0 && list[bq] > key) { list[bq + 1] = list[bq]; --bq; }
                list[bq + 1] = key;
            }
            const int ia = want_a - s_excla;
            g_stats[row] = make_float2(list[ia], list[ia + 1]);
        }
        done = true;
    }
}

// ---------------------------------------------------------------------------
// k_vt: g_value (b,j,h*64+k) -> g_vhi/g_vlo (b*4+h, k, j)  (verbatim)
// ---------------------------------------------------------------------------
__global__ void __launch_bounds__(256) k_vt() {
    __shared__ float ts[64][65];
    const int t = threadIdx.x;
    const int bh = blockIdx.x >> 6, jt = blockIdx.x & 63;
#pragma unroll
    for (int s = 0; s < 4; ++s) {
        int idx = t + 256 * s;
        int jj = idx >> 4, q = idx & 15;
        float4 v = *(const float4*)(g_value +
            ((size_t)(bh >> 2) * NN + jt * 64 + jj) * HID + (bh & 3) * 64 + q * 4);
        ts[jj][q * 4 + 0] = v.x; ts[jj][q * 4 + 1] = v.y;
        ts[jj][q * 4 + 2] = v.z; ts[jj][q * 4 + 3] = v.w;
    }
    __syncthreads();
    const int k = t >> 2, seg = t & 3;
    uint32_t uh[8], ul[8];
#pragma unroll
    for (int e = 0; e < 8; ++e) {
        float v0 = ts[seg * 16 + 2 * e][k], v1 = ts[seg * 16 + 2 * e + 1][k];
        __half h0 = __float2half_rn(v0), h1 = __float2half_rn(v1);
        uh[e] = pk(h0, h1);
        ul[e] = pk(__float2half_rn(v0 - __half2float(h0)),
                   __float2half_rn(v1 - __half2float(h1)));
    }
    size_t dst = ((size_t)(bh * 64 + k)) * NN + jt * 64 + seg * 16;
    *(uint4*)(g_vhi + dst)     = make_uint4(uh[0], uh[1], uh[2], uh[3]);
    *(uint4*)(g_vhi + dst + 8) = make_uint4(uh[4], uh[5], uh[6], uh[7]);
    *(uint4*)(g_vlo + dst)     = make_uint4(ul[0], ul[1], ul[2], ul[3]);
    *(uint4*)(g_vlo + dst + 8) = make_uint4(ul[4], ul[5], ul[6], ul[7]);
}

// ---------------------------------------------------------------------------
// k_mma: CTA = (128 i, h, b). j-tiles of 32. m via prefetched LDG->registers;
// w fp16-hi; 2-term HMMA (w x v_hi, w x v_lo). 3 CTAs/SM.
// ---------------------------------------------------------------------------
__global__ void __launch_bounds__(256, 3) k_mma(const float* __restrict__ m,
                                                const float* __restrict__ r,
                                                float* __restrict__ out) {
    extern __shared__ __align__(16) char sgen[];
    __shared__ float thr_s[128];
    __shared__ float sden[384];
    const int t = threadIdx.x, warp = t >> 5, lane = t & 31;
    const int h = blockIdx.y, bz = blockIdx.z;
    const int i_base = blockIdx.x * 128;
    const int bh64 = (bz * 4 + h) * 64;
    const uint32_t sb = (uint32_t)__cvta_generic_to_shared(sgen);

    const float rv = r[h], r2 = __fmul_rn(rv, rv);
    if (t < 128) {
        float2 st = g_stats[bz * NN + i_base + t];
        thr_s[t] = __fadd_rn(__fmul_rn(0.5f, __fmul_rn(r2, st.x)),
                             __fmul_rn(0.5f, __fmul_rn(r2, st.y)));
    }
    __syncthreads();

    const int i = t >> 1, jh = t & 1;
    const float* mp = m + (size_t)(bz * NN + i_base + i) * NN + jh * 16;
    const float thr_i = thr_s[i];
    float den_acc = 0.f;
    float acc[32];
#pragma unroll
    for (int q = 0; q < 32; ++q) acc[q] = 0.f;

    float4 mr[4];
    // prologue: m tile 0 into registers, v tile 0 via cp.async
#pragma unroll
    for (int q = 0; q < 4; ++q) mr[q] = *(const float4*)(mp + q * 4);
    {
        int k2 = t >> 2, q = t & 3;
        cpa16(sb + VHO + (unsigned)k2 * 80u + (unsigned)q * 16u,
              g_vhi + (size_t)(bh64 + k2) * NN + q * 8);
        cpa16(sb + VLO + (unsigned)k2 * 80u + (unsigned)q * 16u,
              g_vlo + (size_t)(bh64 + k2) * NN + q * 8);
        asm volatile("cp.async.commit_group;");
    }

    for (int c = 0; c < 128; ++c) {
        const unsigned buf = (unsigned)(c & 1);

        // w-stage: exp/mask from registers, fp16-hi, den accumulate
        {
            uint32_t uh[8];
#pragma unroll
            for (int q = 0; q < 4; ++q) {
                float4 mv = mr[q];
                float s0 = __fmul_rn(mv.x, r2), s1 = __fmul_rn(mv.y, r2);
                float s2 = __fmul_rn(mv.z, r2), s3 = __fmul_rn(mv.w, r2);
                float w0 = (s0 <= thr_i) ? __expf(-s0) : 0.f;
                float w1 = (s1 <= thr_i) ? __expf(-s1) : 0.f;
                float w2 = (s2 <= thr_i) ? __expf(-s2) : 0.f;
                float w3 = (s3 <= thr_i) ? __expf(-s3) : 0.f;
                den_acc += (w0 + w1) + (w2 + w3);
                uh[q * 2 + 0] = pk(__float2half_rn(w0), __float2half_rn(w1));
                uh[q * 2 + 1] = pk(__float2half_rn(w2), __float2half_rn(w3));
            }
            char* wd = sgen + WHO + buf * WBS + i * 80 + jh * 32;
            *(uint4*)wd        = make_uint4(uh[0], uh[1], uh[2], uh[3]);
            *(uint4*)(wd + 16) = make_uint4(uh[4], uh[5], uh[6], uh[7]);
        }

        // prefetch next m tile into registers; next v via cp.async
        if (c < 127) {
            const float* src = mp + (c + 1) * 32;
#pragma unroll
            for (int q = 0; q < 4; ++q) mr[q] = *(const float4*)(src + q * 4);
            const int j0n = (c + 1) * 32;
            const unsigned nb = (unsigned)((c + 1) & 1);
            int k2 = t >> 2, q = t & 3;
            cpa16(sb + VHO + nb * VBS + (unsigned)k2 * 80u + (unsigned)q * 16u,
                  g_vhi + (size_t)(bh64 + k2) * NN + j0n + q * 8);
            cpa16(sb + VLO + nb * VBS + (unsigned)k2 * 80u + (unsigned)q * 16u,
                  g_vlo + (size_t)(bh64 + k2) * NN + j0n + q * 8);
            asm volatile("cp.async.commit_group;");
            asm volatile("cp.async.wait_group 1;");
        } else {
            asm volatile("cp.async.wait_group 0;");
        }
        __syncthreads();

        // mma stage: 2 terms (w x v_hi, w x v_lo)
        {
            const int i0 = warp * 16;
            const unsigned arow = (unsigned)(i0 + (lane & 15)) * 80u +
                                  (unsigned)((lane >> 4) << 4);
            const int nb_ = (lane & 7) + ((lane >> 4) << 3);
            const unsigned brow0 = (unsigned)nb_ * 80u + (unsigned)((lane & 8) << 1);
#pragma unroll
            for (int cc = 0; cc < 2; ++cc) {
                uint32_t ah0, ah1, ah2, ah3;
                uint32_t aaddr = sb + WHO + buf * WBS + arow + (unsigned)cc * 32u;
                LDSM4(ah0, ah1, ah2, ah3, aaddr);
#pragma unroll
                for (int g = 0; g < 4; ++g) {
                    uint32_t bh0, bh1, bh2, bh3, bl0, bl1, bl2, bl3;
                    uint32_t baddr = sb + VHO + buf * VBS + brow0 +
                                     (unsigned)(g * 16) * 80u + (unsigned)cc * 32u;
                    LDSM4(bh0, bh1, bh2, bh3, baddr);
                    LDSM4(bl0, bl1, bl2, bl3, baddr + (VLO - VHO));
                    float* d0 = acc + g * 8;
                    float* d1 = acc + g * 8 + 4;
                    MMA(d0, ah0, ah1, ah2, ah3, bh0, bh1);
                    MMA(d0, ah0, ah1, ah2, ah3, bl0, bl1);
                    MMA(d1, ah0, ah1, ah2, ah3, bh2, bh3);
                    MMA(d1, ah0, ah1, ah2, ah3, bl2, bl3);
                }
            }
        }
        __syncthreads();
    }

    sden[t] = den_acc;
    __syncthreads();
    if (t < 128) sden[256 + t] = sden[2 * t] + sden[2 * t + 1];
    __syncthreads();
    const float* dden = sden + 256;
    const int i0 = warp * 16;
    const int r0 = lane >> 2, c0 = (lane & 3) * 2;
    const float inv0 = 1.0f / dden[i0 + r0];
    const float inv1 = 1.0f / dden[i0 + r0 + 8];
    float* ob = out + ((size_t)(bz * NN + i_base + i0)) * HID + h * 64;
#pragma unroll
    for (int nt = 0; nt < 8; ++nt) {
        float v0 = acc[nt * 4 + 0] * inv0, v1 = acc[nt * 4 + 1] * inv0;
        float v2 = acc[nt * 4 + 2] * inv1, v3 = acc[nt * 4 + 3] * inv1;
        float g0 = 0.5f * v0 * (1.0f + erff(v0 * 0.7071067811865475f));
        float g1 = 0.5f * v1 * (1.0f + erff(v1 * 0.7071067811865475f));
        float g2 = 0.5f * v2 * (1.0f + erff(v2 * 0.7071067811865475f));
        float g3 = 0.5f * v3 * (1.0f + erff(v3 * 0.7071067811865475f));
        *(float2*)(ob + (size_t)r0 * HID + nt * 8 + c0)       = make_float2(g0, g1);
        *(float2*)(ob + (size_t)(r0 + 8) * HID + nt * 8 + c0) = make_float2(g2, g3);
    }
}

// ---------------------------------------------------------------------------
extern "C" void kernel_launch(void* const* d_in, const int* in_sizes, int n_in,
                              void* d_out, int out_size) {
    const float *m = nullptr, *x = nullptr, *r = nullptr, *w = nullptr;
    for (int i = 0; i < n_in; ++i) {
        int s = in_sizes[i];
        if      (s == 33554432) m = (const float*)d_in[i];
        else if (s == 2097152)  x = (const float*)d_in[i];
        else if (s == 4)        r = (const float*)d_in[i];
        else if (s == 65536)    w = (const float*)d_in[i];
    }
    float* out = (float*)d_out;

    cudaFuncSetAttribute(k_mma, cudaFuncAttributeMaxDynamicSharedMemorySize, SMT);

    k_pre<<<1024 + 8192, 256>>>(x, w, m);
    k_vt<<<512, 256>>>();
    k_mma<<<dim3(32, 4, 2), 256, SMT>>>(m, r, out);
}